// round 2
// baseline (speedup 1.0000x reference)
#include <cuda_runtime.h>
#include <cuda_bf16.h>
#include <cstdint>

#define N_NODES 50000
#define N_EDGES 800000
#define FIN 256
#define HF 256          // OUT_FEAT * NHEAD
#define NHEAD 4
#define ALPHA 0.2f

// ---------------- scratch (static device globals; no allocation) ----------------
__device__ float g_h[(size_t)N_NODES * HF];     // 51.2 MB  h = x@W
__device__ float g_hl[N_NODES * NHEAD];
__device__ float g_hr[N_NODES * NHEAD];
__device__ int   g_deg[N_NODES];
__device__ int   g_off[N_NODES];
__device__ int   g_cur[N_NODES];
__device__ int   g_col[N_EDGES];

// ---------------- GEMM: h = x[50000,256] @ W[256,256] ----------------
#define BM 128
#define BN 64
#define BK 16
__global__ void gemm_kernel(const float* __restrict__ A, const float* __restrict__ B) {
    __shared__ float As[BK][BM + 4];
    __shared__ float Bs[BK][BN + 4];

    const int tid = threadIdx.x;          // 256 threads
    const int tx = tid & 15;              // 0..15 -> 4 cols each
    const int ty = tid >> 4;              // 0..15 -> 8 rows each
    const int rowBase = blockIdx.y * BM;
    const int colBase = blockIdx.x * BN;

    float c[8][4];
#pragma unroll
    for (int i = 0; i < 8; i++)
#pragma unroll
        for (int j = 0; j < 4; j++) c[i][j] = 0.0f;

    for (int k0 = 0; k0 < FIN; k0 += BK) {
        // A tile: 128x16 -> 512 float4, 2 per thread, stored transposed
#pragma unroll
        for (int r = 0; r < 2; r++) {
            int p = tid + r * 256;        // 0..511
            int arow = p >> 2;            // 0..127
            int ac4 = p & 3;              // 0..3
            int grow = rowBase + arow;
            float4 v = make_float4(0.f, 0.f, 0.f, 0.f);
            if (grow < N_NODES)
                v = *(const float4*)(A + (size_t)grow * FIN + k0 + ac4 * 4);
            As[ac4 * 4 + 0][arow] = v.x;
            As[ac4 * 4 + 1][arow] = v.y;
            As[ac4 * 4 + 2][arow] = v.z;
            As[ac4 * 4 + 3][arow] = v.w;
        }
        // B tile: 16x64 -> 256 float4, 1 per thread
        {
            int brow = tid >> 4;          // 0..15
            int bc4 = tid & 15;           // 0..15
            float4 v = *(const float4*)(B + (size_t)(k0 + brow) * HF + colBase + bc4 * 4);
            *(float4*)&Bs[brow][bc4 * 4] = v;
        }
        __syncthreads();

#pragma unroll
        for (int kk = 0; kk < BK; kk++) {
            float a[8], b[4];
#pragma unroll
            for (int i = 0; i < 8; i++) a[i] = As[kk][ty * 8 + i];
#pragma unroll
            for (int j = 0; j < 4; j++) b[j] = Bs[kk][tx * 4 + j];
#pragma unroll
            for (int i = 0; i < 8; i++)
#pragma unroll
                for (int j = 0; j < 4; j++) c[i][j] = fmaf(a[i], b[j], c[i][j]);
        }
        __syncthreads();
    }

#pragma unroll
    for (int i = 0; i < 8; i++) {
        int grow = rowBase + ty * 8 + i;
        if (grow < N_NODES) {
            float4 v = make_float4(c[i][0], c[i][1], c[i][2], c[i][3]);
            *(float4*)(g_h + (size_t)grow * HF + colBase + tx * 4) = v;
        }
    }
}

// ---------------- h_l / h_r: per-node, per-head dot with a_l / a_r ----------------
__global__ void hlhr_kernel(const float* __restrict__ a_l, const float* __restrict__ a_r) {
    int gw = (blockIdx.x * blockDim.x + threadIdx.x) >> 5;
    if (gw >= N_NODES) return;
    int lane = threadIdx.x & 31;
    int head = lane >> 3;                 // lane*8 .. lane*8+7 all within head lane/8

    const float* hp = g_h + (size_t)gw * HF + lane * 8;
    float sl = 0.f, sr = 0.f;
#pragma unroll
    for (int j = 0; j < 8; j++) {
        float hv = hp[j];
        sl = fmaf(hv, a_l[lane * 8 + j], sl);
        sr = fmaf(hv, a_r[lane * 8 + j], sr);
    }
    // reduce within 8-lane head groups
#pragma unroll
    for (int off = 4; off; off >>= 1) {
        sl += __shfl_down_sync(0xffffffffu, sl, off, 8);
        sr += __shfl_down_sync(0xffffffffu, sr, off, 8);
    }
    if ((lane & 7) == 0) {
        g_hl[gw * NHEAD + head] = sl;
        g_hr[gw * NHEAD + head] = sr;
    }
}

// ---------------- CSR build ----------------
__global__ void zero_deg_kernel() {
    int i = blockIdx.x * blockDim.x + threadIdx.x;
    if (i < N_NODES) g_deg[i] = 0;
}

__global__ void hist_kernel(const int* __restrict__ edge) {
    int i = blockIdx.x * blockDim.x + threadIdx.x;
    if (i < N_EDGES) atomicAdd(&g_deg[edge[i]], 1);
}

// single-block 2-level exclusive scan over 50000 degrees
__global__ void scan_kernel() {
    __shared__ int partial[1024];
    const int t = threadIdx.x;
    const int CH = (N_NODES + 1023) / 1024;   // 49
    int beg = t * CH;
    int end = beg + CH; if (end > N_NODES) end = N_NODES;
    int s = 0;
    for (int i = beg; i < end; i++) s += g_deg[i];
    partial[t] = s;
    __syncthreads();
    // inclusive Hillis-Steele
    for (int off = 1; off < 1024; off <<= 1) {
        int v = (t >= off) ? partial[t - off] : 0;
        __syncthreads();
        partial[t] += v;
        __syncthreads();
    }
    int run = (t == 0) ? 0 : partial[t - 1];
    for (int i = beg; i < end; i++) {
        g_off[i] = run;
        g_cur[i] = run;
        run += g_deg[i];
    }
}

__global__ void scatter_kernel(const int* __restrict__ edge) {
    int i = blockIdx.x * blockDim.x + threadIdx.x;
    if (i < N_EDGES) {
        int r = edge[i];
        int c = edge[N_EDGES + i];
        int pos = atomicAdd(&g_cur[r], 1);
        g_col[pos] = c;
    }
}

// ---------------- aggregation: softmax over incoming edges + weighted sum ----------------
__global__ void aggregate_kernel(float* __restrict__ out) {
    int gw = (blockIdx.x * blockDim.x + threadIdx.x) >> 5;
    if (gw >= N_NODES) return;
    const int lane = threadIdx.x & 31;
    const int head = lane >> 3;

    const int start = g_off[gw];
    const int d = g_deg[gw];

    const float hl0 = g_hl[gw * NHEAD + 0];
    const float hl1 = g_hl[gw * NHEAD + 1];
    const float hl2 = g_hl[gw * NHEAD + 2];
    const float hl3 = g_hl[gw * NHEAD + 3];

    // pass A: per-head max over edges (lanes stride edges)
    float m0 = -1e30f, m1 = -1e30f, m2 = -1e30f, m3 = -1e30f;
    for (int k = lane; k < d; k += 32) {
        int c = g_col[start + k];
        const float* hr = g_hr + (size_t)c * NHEAD;
        float e0 = hl0 + hr[0]; e0 = e0 > 0.f ? e0 : ALPHA * e0; m0 = fmaxf(m0, e0);
        float e1 = hl1 + hr[1]; e1 = e1 > 0.f ? e1 : ALPHA * e1; m1 = fmaxf(m1, e1);
        float e2 = hl2 + hr[2]; e2 = e2 > 0.f ? e2 : ALPHA * e2; m2 = fmaxf(m2, e2);
        float e3 = hl3 + hr[3]; e3 = e3 > 0.f ? e3 : ALPHA * e3; m3 = fmaxf(m3, e3);
    }
#pragma unroll
    for (int off = 16; off; off >>= 1) {
        m0 = fmaxf(m0, __shfl_xor_sync(0xffffffffu, m0, off));
        m1 = fmaxf(m1, __shfl_xor_sync(0xffffffffu, m1, off));
        m2 = fmaxf(m2, __shfl_xor_sync(0xffffffffu, m2, off));
        m3 = fmaxf(m3, __shfl_xor_sync(0xffffffffu, m3, off));
    }
    const float mh = (head == 0) ? m0 : (head == 1) ? m1 : (head == 2) ? m2 : m3;
    const float hlh = (head == 0) ? hl0 : (head == 1) ? hl1 : (head == 2) ? hl2 : hl3;

    // pass B: whole warp walks edges sequentially; each lane owns 8 features
    float denom = 0.f;
    float a0 = 0.f, a1 = 0.f, a2 = 0.f, a3 = 0.f, a4 = 0.f, a5 = 0.f, a6 = 0.f, a7 = 0.f;
    for (int k = 0; k < d; k++) {
        int c = g_col[start + k];                     // broadcast
        float e = hlh + g_hr[(size_t)c * NHEAD + head];
        e = e > 0.f ? e : ALPHA * e;
        float w = __expf(e - mh);
        denom += w;
        const float4* hp = (const float4*)(g_h + (size_t)c * HF + lane * 8);
        float4 v0 = hp[0];
        float4 v1 = hp[1];
        a0 = fmaf(w, v0.x, a0); a1 = fmaf(w, v0.y, a1);
        a2 = fmaf(w, v0.z, a2); a3 = fmaf(w, v0.w, a3);
        a4 = fmaf(w, v1.x, a4); a5 = fmaf(w, v1.y, a5);
        a6 = fmaf(w, v1.z, a6); a7 = fmaf(w, v1.w, a7);
    }
    float inv = 1.0f / fmaxf(denom, 1e-16f);
    float4 o0 = make_float4(a0 * inv, a1 * inv, a2 * inv, a3 * inv);
    float4 o1 = make_float4(a4 * inv, a5 * inv, a6 * inv, a7 * inv);
    float* op = out + (size_t)gw * HF + lane * 8;
    *(float4*)(op) = o0;
    *(float4*)(op + 4) = o1;
}

// ---------------- launch ----------------
extern "C" void kernel_launch(void* const* d_in, const int* in_sizes, int n_in,
                              void* d_out, int out_size) {
    const float* x    = (const float*)d_in[0];
    const int*   edge = (const int*)d_in[1];     // int32: [2, E] (row; col)
    const float* W    = (const float*)d_in[2];
    const float* a_l  = (const float*)d_in[3];
    const float* a_r  = (const float*)d_in[4];
    float* out = (float*)d_out;

    dim3 ggrid(HF / BN, (N_NODES + BM - 1) / BM);    // (4, 391)
    gemm_kernel<<<ggrid, 256>>>(x, W);

    hlhr_kernel<<<(N_NODES * 32 + 255) / 256, 256>>>(a_l, a_r);

    zero_deg_kernel<<<(N_NODES + 255) / 256, 256>>>();
    hist_kernel<<<(N_EDGES + 255) / 256, 256>>>(edge);
    scan_kernel<<<1, 1024>>>();
    scatter_kernel<<<(N_EDGES + 255) / 256, 256>>>(edge);

    aggregate_kernel<<<(N_NODES * 32 + 255) / 256, 256>>>(out);
}